// round 7
// baseline (speedup 1.0000x reference)
#include <cuda_runtime.h>
#include <math.h>

#define B   32
#define NF  128
#define DE  256
#define DH  512
#define G   2
#define SL  8

// ---- device scratch (no allocations allowed) ----
__device__ float g_query[B * DE];
__device__ float g_attin[B * NF * G];
__device__ float g_P[B * NF * NF];       // M @ M
__device__ float g_R[B * NF * NF];       // 0.81*M + 0.729*P
__device__ float g_finalT[B * NF * NF];  // final mask, transposed [b][m][n]
__device__ float g_sig[B * NF * NF];     // sigmoid(fe . q), layout [b][m][n]
__device__ unsigned g_ctr_query;
__device__ unsigned g_ctr_prepA;

__device__ __forceinline__ void cp_async16(void* smem_dst, const void* gmem_src) {
    unsigned sa = (unsigned)__cvta_generic_to_shared(smem_dst);
    asm volatile("cp.async.ca.shared.global [%0], [%1], 16;" :: "r"(sa), "l"(gmem_src));
}

// ============================================================================
// Kernel 0: reset intra-launch ordering counters (graph-replay determinism).
// ============================================================================
__global__ void k0_reset() {
    g_ctr_query = 0;
    g_ctr_prepA = 0;
}

// ============================================================================
// Mega kernel: one launch, 4640 blocks of 256 threads.
//   bids    0-  31 : query+att_in  -> bump g_ctr_query
//   bids   32-1055 : sigma ids    0-1023  (spin g_ctr_query == 32)
//   bids 1056-1311 : prepA (P = M@M sparse, R = 0.81M+0.729P) -> g_ctr_prepA
//   bids 1312-2335 : sigma ids 1024-2047
//   bids 2336-2591 : prepB (final = M + 0.9P + P@R -> finalT; spin prepA==256)
//   bids 2592-4639 : sigma ids 2048-4095
// Producers have lower bids than their spinners -> forward progress safe.
// ============================================================================
__global__ __launch_bounds__(256) void k_mega(
    const float* __restrict__ relmask, const float* __restrict__ fe,
    const float* __restrict__ c_i, const float* __restrict__ W,
    const float* __restrict__ bias,
    const float* __restrict__ att_stack, const float* __restrict__ stack_ptr)
{
    __shared__ __align__(16) char shraw[49152];
    int bid = blockIdx.x;
    int t = threadIdx.x;

    // ---------------------------------------------------------------- query
    if (bid < 32) {
        int b = bid;
        float* qc = (float*)shraw;
        qc[t]       = c_i[b * DH + t];
        qc[t + 256] = c_i[b * DH + t + 256];
        __syncthreads();

        int w = t >> 5, lane = t & 31;
        for (int d = w; d < DE; d += 8) {
            const float* Wr = W + (size_t)d * DH;
            float s = 0.f;
            #pragma unroll
            for (int i = 0; i < DH / 32; i++)
                s += Wr[lane + 32 * i] * qc[lane + 32 * i];
            #pragma unroll
            for (int o = 16; o; o >>= 1) s += __shfl_xor_sync(~0u, s, o);
            if (lane == 0) g_query[b * DE + d] = s + bias[d];
        }
        {
            int n = t >> 1, g = t & 1;
            const float* as = att_stack + (((size_t)b * NF + n) * G + g) * SL;
            const float* sp = stack_ptr + b * SL;
            float s = 0.f;
            #pragma unroll
            for (int ss = 0; ss < SL; ss++) s += as[ss] * sp[ss];
            g_attin[(b * NF + n) * G + g] = s;
        }
        __threadfence();
        __syncthreads();
        if (t == 0) atomicAdd(&g_ctr_query, 1u);
        return;
    }

    // ---------------------------------------------------------------- prepA
    if (bid >= 1056 && bid < 1312) {
        int id = bid - 1056;
        int b  = id >> 3;
        int n0 = (id & 7) * 16;
        const float* Mb = relmask + (size_t)b * NF * NF;

        float (*csh)[NF] = (float(*)[NF])shraw;                   // 8KB
        float (*msh)[32][NF] = (float(*)[32][NF])(shraw + 8192);  // 32KB

        {
            const float4* src = (const float4*)(Mb + (size_t)n0 * NF);
            float4* dst = (float4*)&csh[0][0];
            cp_async16(dst + t,       src + t);
            cp_async16(dst + t + 256, src + t + 256);
        }
        {
            const float4* src = (const float4*)Mb;
            float4* dst = (float4*)&msh[0][0][0];
            #pragma unroll
            for (int i = 0; i < 4; i++)
                cp_async16(dst + t + 256 * i, src + t + 256 * i);
        }
        asm volatile("cp.async.commit_group;");
        asm volatile("cp.async.wait_group 0;");
        __syncthreads();

        int tn = (t >> 5) * 2;
        int tm = (t & 31) * 4;

        float acc0[4] = {}, acc1[4] = {};
        for (int kt = 0; kt < 4; kt++) {
            if (kt < 3) {
                const float4* src = (const float4*)(Mb + (size_t)(kt + 1) * 32 * NF);
                float4* dst = (float4*)&msh[(kt + 1) & 1][0][0];
                #pragma unroll
                for (int i = 0; i < 4; i++)
                    cp_async16(dst + t + 256 * i, src + t + 256 * i);
                asm volatile("cp.async.commit_group;");
                asm volatile("cp.async.wait_group 1;");
            } else {
                asm volatile("cp.async.wait_group 0;");
            }
            __syncthreads();

            const float (*mb)[NF] = msh[kt & 1];
            #pragma unroll
            for (int kk4 = 0; kk4 < 8; kk4++) {
                float cva[4], cvb[4];
                *(float4*)cva = *(const float4*)&csh[tn + 0][kt * 32 + kk4 * 4];
                *(float4*)cvb = *(const float4*)&csh[tn + 1][kt * 32 + kk4 * 4];
                #pragma unroll
                for (int j = 0; j < 4; j++) {
                    float ca = cva[j], cb2 = cvb[j];
                    if (ca != 0.f || cb2 != 0.f) {   // warp-uniform skip (~90%)
                        float4 mv = *(const float4*)&mb[kk4 * 4 + j][tm];
                        acc0[0] += ca * mv.x;  acc0[1] += ca * mv.y;
                        acc0[2] += ca * mv.z;  acc0[3] += ca * mv.w;
                        acc1[0] += cb2 * mv.x; acc1[1] += cb2 * mv.y;
                        acc1[2] += cb2 * mv.z; acc1[3] += cb2 * mv.w;
                    }
                }
            }
            __syncthreads();
        }

        #pragma unroll
        for (int i = 0; i < 2; i++) {
            const float* acc = (i == 0) ? acc0 : acc1;
            size_t base = ((size_t)b * NF + n0 + tn + i) * NF + tm;
            float4 p = make_float4(acc[0], acc[1], acc[2], acc[3]);
            *(float4*)&g_P[base] = p;
            float4 mm = *(const float4*)&csh[tn + i][tm];
            float4 r;
            r.x = 0.81f * mm.x + 0.729f * p.x;
            r.y = 0.81f * mm.y + 0.729f * p.y;
            r.z = 0.81f * mm.z + 0.729f * p.z;
            r.w = 0.81f * mm.w + 0.729f * p.w;
            *(float4*)&g_R[base] = r;
        }
        __threadfence();
        __syncthreads();
        if (t == 0) atomicAdd(&g_ctr_prepA, 1u);
        return;
    }

    // ---------------------------------------------------------------- prepB
    if (bid >= 2336 && bid < 2592) {
        int id = bid - 2336;
        int b  = id >> 3;
        int n0 = (id & 7) * 16;
        const float* Pb = g_P + (size_t)b * NF * NF;
        const float* Rb = g_R + (size_t)b * NF * NF;
        const float* Mb = relmask + (size_t)b * NF * NF;

        if (t == 0) {
            while (*(volatile unsigned*)&g_ctr_prepA < 256u) __nanosleep(64);
            __threadfence();
        }
        __syncthreads();

        float (*csh)[NF] = (float(*)[NF])shraw;                     // 8KB: P rows
        float (*msm)[NF] = (float(*)[NF])(shraw + 8192);            // 8KB: M rows
        float (*msh)[32][NF] = (float(*)[32][NF])(shraw + 16384);   // 32KB

        {
            const float4* srcP = (const float4*)(Pb + (size_t)n0 * NF);
            const float4* srcM = (const float4*)(Mb + (size_t)n0 * NF);
            float4* dstP = (float4*)&csh[0][0];
            float4* dstM = (float4*)&msm[0][0];
            cp_async16(dstP + t,       srcP + t);
            cp_async16(dstP + t + 256, srcP + t + 256);
            cp_async16(dstM + t,       srcM + t);
            cp_async16(dstM + t + 256, srcM + t + 256);
        }
        {
            const float4* src = (const float4*)Rb;
            float4* dst = (float4*)&msh[0][0][0];
            #pragma unroll
            for (int i = 0; i < 4; i++)
                cp_async16(dst + t + 256 * i, src + t + 256 * i);
        }
        asm volatile("cp.async.commit_group;");
        asm volatile("cp.async.wait_group 0;");
        __syncthreads();

        int tn = (t >> 5) * 2;
        int tm = (t & 31) * 4;

        float acc0[4] = {}, acc1[4] = {};
        for (int kt = 0; kt < 4; kt++) {
            if (kt < 3) {
                const float4* src = (const float4*)(Rb + (size_t)(kt + 1) * 32 * NF);
                float4* dst = (float4*)&msh[(kt + 1) & 1][0][0];
                #pragma unroll
                for (int i = 0; i < 4; i++)
                    cp_async16(dst + t + 256 * i, src + t + 256 * i);
                asm volatile("cp.async.commit_group;");
                asm volatile("cp.async.wait_group 1;");
            } else {
                asm volatile("cp.async.wait_group 0;");
            }
            __syncthreads();

            const float (*mb)[NF] = msh[kt & 1];
            #pragma unroll
            for (int kk4 = 0; kk4 < 8; kk4++) {
                float cva[4], cvb[4];
                *(float4*)cva = *(const float4*)&csh[tn + 0][kt * 32 + kk4 * 4];
                *(float4*)cvb = *(const float4*)&csh[tn + 1][kt * 32 + kk4 * 4];
                #pragma unroll
                for (int j = 0; j < 4; j++) {
                    float4 mv = *(const float4*)&mb[kk4 * 4 + j][tm];
                    acc0[0] += cva[j] * mv.x; acc0[1] += cva[j] * mv.y;
                    acc0[2] += cva[j] * mv.z; acc0[3] += cva[j] * mv.w;
                    acc1[0] += cvb[j] * mv.x; acc1[1] += cvb[j] * mv.y;
                    acc1[2] += cvb[j] * mv.z; acc1[3] += cvb[j] * mv.w;
                }
            }
            __syncthreads();
        }

        float4 f0, f1;
        {
            float4 mm = *(const float4*)&msm[tn + 0][tm];
            float4 pp = *(const float4*)&csh[tn + 0][tm];
            f0.x = mm.x + 0.9f * pp.x + acc0[0];
            f0.y = mm.y + 0.9f * pp.y + acc0[1];
            f0.z = mm.z + 0.9f * pp.z + acc0[2];
            f0.w = mm.w + 0.9f * pp.w + acc0[3];
            mm = *(const float4*)&msm[tn + 1][tm];
            pp = *(const float4*)&csh[tn + 1][tm];
            f1.x = mm.x + 0.9f * pp.x + acc1[0];
            f1.y = mm.y + 0.9f * pp.y + acc1[1];
            f1.z = mm.z + 0.9f * pp.z + acc1[2];
            f1.w = mm.w + 0.9f * pp.w + acc1[3];
        }
        __syncthreads();
        *(float4*)&csh[tn + 0][tm] = f0;
        *(float4*)&csh[tn + 1][tm] = f1;
        __syncthreads();
        {
            int m = t >> 1, half = (t & 1) * 8;
            float v[8];
            #pragma unroll
            for (int i = 0; i < 8; i++) v[i] = csh[half + i][m];
            float* dstT = g_finalT + ((size_t)b * NF + m) * NF + n0 + half;
            *(float4*)&dstT[0] = make_float4(v[0], v[1], v[2], v[3]);
            *(float4*)&dstT[4] = make_float4(v[4], v[5], v[6], v[7]);
        }
        return;
    }

    // ---------------------------------------------------------------- sigma
    int id = (bid < 1056) ? (bid - 32) : (bid < 2336 ? bid - 288 : bid - 544);
    int b = id >> 7;
    int m = id & 127;
    float* qsh = (float*)shraw;          // 1KB
    float* sig = qsh + DE;               // 0.5KB

    if (t == 0) {
        while (*(volatile unsigned*)&g_ctr_query < 32u) __nanosleep(64);
        __threadfence();
    }
    __syncthreads();
    qsh[t] = g_query[b * DE + t];
    __syncthreads();

    int w = t >> 5, lane = t & 31;
    int qq = lane >> 3, sub = lane & 7;
    const float4* qp = (const float4*)qsh;
    const float* febase = fe + (((size_t)b * NF) * NF + m) * DE;

    float4 cur[8];
    {
        const float4* row = (const float4*)(febase + (size_t)(w + 8 * qq) * NF * DE);
        #pragma unroll
        for (int c = 0; c < 8; c++) cur[c] = __ldcs(&row[sub + 8 * c]);
    }

    #pragma unroll
    for (int j = 0; j < 4; j++) {
        float4 nxt[8];
        if (j < 3) {
            int n2 = w + 8 * (4 * (j + 1) + qq);
            const float4* row = (const float4*)(febase + (size_t)n2 * NF * DE);
            #pragma unroll
            for (int c = 0; c < 8; c++) nxt[c] = __ldcs(&row[sub + 8 * c]);
        }

        float sA = 0.f, sB = 0.f;
        #pragma unroll
        for (int c = 0; c < 8; c += 2) {
            float4 q0 = qp[sub + 8 * c];
            float4 q1 = qp[sub + 8 * (c + 1)];
            sA += cur[c].x * q0.x + cur[c].y * q0.y
                + cur[c].z * q0.z + cur[c].w * q0.w;
            sB += cur[c+1].x * q1.x + cur[c+1].y * q1.y
                + cur[c+1].z * q1.z + cur[c+1].w * q1.w;
        }
        float s = sA + sB;
        s += __shfl_xor_sync(~0u, s, 1);
        s += __shfl_xor_sync(~0u, s, 2);
        s += __shfl_xor_sync(~0u, s, 4);
        int n = w + 8 * (4 * j + qq);
        if (sub == 0) sig[n] = 1.f / (1.f + __expf(-s));

        #pragma unroll
        for (int c = 0; c < 8; c++) cur[c] = nxt[c];
    }
    __syncthreads();
    if (t < NF)
        g_sig[((size_t)b * NF + m) * NF + t] = sig[t];
}

// ============================================================================
// Kernel 3: masked contraction + norm + blend + all outputs.
// grid(B), block(512).  Each warp handles 8 m-rows; per row one float4/lane.
// ============================================================================
__global__ __launch_bounds__(512) void k3_final(
    const float* __restrict__ att_stack, const float* __restrict__ stack_ptr,
    float* __restrict__ out)
{
    int b = blockIdx.x;
    int t = threadIdx.x;
    __shared__ float ash[NF * G];
    __shared__ float att[NF * G];
    __shared__ float norm[G];
    __shared__ float sps[SL];

    if (t < NF * G) ash[t] = g_attin[b * NF * G + t];
    if (t < SL) sps[t] = stack_ptr[b * SL + t];
    __syncthreads();

    int w = t >> 5, lane = t & 31;
    const float4* ap = (const float4*)ash;
    float4 a01 = ap[2 * lane], a23 = ap[2 * lane + 1];

    #pragma unroll
    for (int r = 0; r < 8; r++) {
        int m = w + 16 * r;
        const float4* fr = (const float4*)(g_finalT + ((size_t)b * NF + m) * NF);
        const float4* sr = (const float4*)(g_sig    + ((size_t)b * NF + m) * NF);
        float4 f = fr[lane];
        float4 s = sr[lane];
        float w0 = f.x * s.x, w1 = f.y * s.y, w2 = f.z * s.z, w3 = f.w * s.w;
        float p0 = w0 * a01.x + w1 * a01.z + w2 * a23.x + w3 * a23.z;
        float p1 = w0 * a01.y + w1 * a01.w + w2 * a23.y + w3 * a23.w;
        #pragma unroll
        for (int o = 16; o; o >>= 1) {
            p0 += __shfl_xor_sync(~0u, p0, o);
            p1 += __shfl_xor_sync(~0u, p1, o);
        }
        if (lane == 0) { att[m * 2] = p0; att[m * 2 + 1] = p1; }
    }
    __syncthreads();

    if (t < 64) {
        int g = t >> 5, ln = t & 31;
        float mx = -1e30f;
        for (int i = ln; i < NF; i += 32) mx = fmaxf(mx, att[i * G + g]);
        #pragma unroll
        for (int o = 16; o; o >>= 1) mx = fmaxf(mx, __shfl_xor_sync(~0u, mx, o));
        if (ln == 0) norm[g] = (mx <= 1.f) ? 1.f : mx;
    }
    __syncthreads();

    const float* asb = att_stack + (size_t)b * NF * G * SL;
    float* ob = out + (size_t)b * NF * G * SL;
    for (int idx = t; idx < NF * G * SL; idx += 512) {
        int s = idx & 7;
        int g = (idx >> 3) & 1;
        int n = idx >> 4;
        float a  = att[n * G + g] / norm[g];
        float sp = sps[s];
        ob[idx] = a * sp + asb[idx] * (1.f - sp);
    }
    if (t < SL) out[(size_t)B * NF * G * SL + b * SL + t] = sps[t];
    float* z = out + (size_t)B * NF * G * SL + (size_t)B * SL;
    for (int i = t; i < DH; i += 512) {
        z[(size_t)b * DH + i] = 0.f;
        z[(size_t)B * DH + (size_t)b * DH + i] = 0.f;
    }
}

// ============================================================================
extern "C" void kernel_launch(void* const* d_in, const int* in_sizes, int n_in,
                              void* d_out, int out_size)
{
    const float* feat_edge = (const float*)d_in[2];
    const float* c_i       = (const float*)d_in[3];
    const float* relmask   = (const float*)d_in[4];
    const float* att_stack = (const float*)d_in[5];
    const float* stack_ptr = (const float*)d_in[6];
    const float* map_c_w   = (const float*)d_in[8];
    const float* map_c_b   = (const float*)d_in[9];
    float* out = (float*)d_out;

    k0_reset<<<1, 1>>>();
    k_mega<<<4640, 256>>>(relmask, feat_edge, c_i, map_c_w, map_c_b,
                          att_stack, stack_ptr);
    k3_final<<<B, 512>>>(att_stack, stack_ptr, out);
}

// round 8
// speedup vs baseline: 1.0542x; 1.0542x over previous
#include <cuda_runtime.h>
#include <math.h>

#define B   32
#define NF  128
#define DE  256
#define DH  512
#define G   2
#define SL  8

// ---- device scratch (no allocations allowed) ----
__device__ float g_query[B * DE];
__device__ float g_attin[B * NF * G];
__device__ float g_P[B * NF * NF];       // M @ M (integer counts as float)
__device__ float g_R[B * NF * NF];       // 0.81*M + 0.729*P
__device__ float g_finalT[B * NF * NF];  // final mask, transposed [b][m][n]
__device__ float g_sig[B * NF * NF];     // sigmoid(fe . q), layout [b][m][n]

__device__ __forceinline__ void cp_async16(void* smem_dst, const void* gmem_src) {
    unsigned sa = (unsigned)__cvta_generic_to_shared(smem_dst);
    asm volatile("cp.async.ca.shared.global [%0], [%1], 16;" :: "r"(sa), "l"(gmem_src));
}

// ============================================================================
// Kernel 1: bid < 32  : P = M@M via bitmask+popcount (M is exactly {0,1});
//                       R = 0.81*M + 0.729*P.  One block per batch.
//           bid >= 32 : query = c_i@W^T + b ; att_in einsum.
// grid(64), block(256).
// ============================================================================
__global__ __launch_bounds__(256) void k1_bitP_query(
    const float* __restrict__ relmask,
    const float* __restrict__ c_i, const float* __restrict__ W,
    const float* __restrict__ bias,
    const float* __restrict__ att_stack, const float* __restrict__ stack_ptr)
{
    int bid = blockIdx.x;
    int t = threadIdx.x;

    if (bid >= 32) {
        int b = bid - 32;
        __shared__ float qc[DH];
        qc[t]       = c_i[b * DH + t];
        qc[t + 256] = c_i[b * DH + t + 256];
        __syncthreads();

        int w = t >> 5, lane = t & 31;
        for (int d = w; d < DE; d += 8) {
            const float* Wr = W + (size_t)d * DH;
            float s = 0.f;
            #pragma unroll
            for (int i = 0; i < DH / 32; i++)
                s += Wr[lane + 32 * i] * qc[lane + 32 * i];
            #pragma unroll
            for (int o = 16; o; o >>= 1) s += __shfl_xor_sync(~0u, s, o);
            if (lane == 0) g_query[b * DE + d] = s + bias[d];
        }
        {
            int n = t >> 1, g = t & 1;
            const float* as = att_stack + (((size_t)b * NF + n) * G + g) * SL;
            const float* sp = stack_ptr + b * SL;
            float s = 0.f;
            #pragma unroll
            for (int ss = 0; ss < SL; ss++) s += as[ss] * sp[ss];
            g_attin[(b * NF + n) * G + g] = s;
        }
        return;
    }

    // ---------------- bit-packed P = M@M ----------------
    int b = bid;
    const float* Mb = relmask + (size_t)b * NF * NF;

    __shared__ unsigned rowbits[NF][4];      // row n bits over k
    __shared__ unsigned colbits[NF][5];      // col m bits over k (padded)

    int w = t >> 5, lane = t & 31;

    // pack rows via ballot: 512 words, 64 per warp, fully coalesced loads
    for (int Wd = w; Wd < 512; Wd += 8) {
        int r = Wd >> 2, ww = Wd & 3;
        float v = Mb[r * NF + ww * 32 + lane];
        unsigned bal = __ballot_sync(~0u, v != 0.f);
        if (lane == 0) rowbits[r][ww] = bal;
    }
    __syncthreads();

    // bit transpose: colbits[m][w] bit j = rowbits[32w+j] bit m
    for (int p = t; p < 512; p += 256) {
        int m = p >> 2, ww = p & 3;
        unsigned x = 0;
        #pragma unroll
        for (int j = 0; j < 32; j++)
            x |= (((rowbits[32 * ww + j][m >> 5] >> (m & 31)) & 1u) << j);
        colbits[m][ww] = x;
    }
    __syncthreads();

    // P[n][m] = popc over 4 words; R = 0.81*M + 0.729*P  (M from bits)
    float* Pb = g_P + (size_t)b * NF * NF;
    float* Rb = g_R + (size_t)b * NF * NF;
    for (int o = t; o < NF * NF; o += 256) {
        int n = o >> 7, m = o & 127;
        unsigned c = __popc(rowbits[n][0] & colbits[m][0])
                   + __popc(rowbits[n][1] & colbits[m][1])
                   + __popc(rowbits[n][2] & colbits[m][2])
                   + __popc(rowbits[n][3] & colbits[m][3]);
        float p = (float)c;
        float mm = (float)((rowbits[n][m >> 5] >> (m & 31)) & 1u);
        Pb[o] = p;
        Rb[o] = 0.81f * mm + 0.729f * p;
    }
}

// ============================================================================
// Kernel 2: combined launch.
//   bid < 256  : prepB — final = M + 0.9P + P@R, write final^T.
//   bid >= 256 : sigma stream — sig[b,m,n] = sigmoid(fe[b,n,m,:].q[b,:]).
// grid(256 + B*NF), block(256).  Shared memory overlaid (48KB).
// ============================================================================
__global__ __launch_bounds__(256) void k2_prepB_sigma(
    const float* __restrict__ relmask, const float* __restrict__ fe)
{
    __shared__ __align__(16) char shraw[49152];
    int bid = blockIdx.x;
    int t = threadIdx.x;

    if (bid < 256) {
        // ---------------- prepB ----------------
        int b  = bid >> 3;
        int n0 = (bid & 7) * 16;
        const float* Pb = g_P + (size_t)b * NF * NF;
        const float* Rb = g_R + (size_t)b * NF * NF;
        const float* Mb = relmask + (size_t)b * NF * NF;

        float (*csh)[NF] = (float(*)[NF])shraw;                 // 8KB: P rows
        float (*msm)[NF] = (float(*)[NF])(shraw + 8192);        // 8KB: M rows
        float (*msh)[32][NF] = (float(*)[32][NF])(shraw + 16384); // 32KB

        {
            const float4* srcP = (const float4*)(Pb + (size_t)n0 * NF);
            const float4* srcM = (const float4*)(Mb + (size_t)n0 * NF);
            float4* dstP = (float4*)&csh[0][0];
            float4* dstM = (float4*)&msm[0][0];
            cp_async16(dstP + t,       srcP + t);
            cp_async16(dstP + t + 256, srcP + t + 256);
            cp_async16(dstM + t,       srcM + t);
            cp_async16(dstM + t + 256, srcM + t + 256);
        }
        {
            const float4* src = (const float4*)Rb;
            float4* dst = (float4*)&msh[0][0][0];
            #pragma unroll
            for (int i = 0; i < 4; i++)
                cp_async16(dst + t + 256 * i, src + t + 256 * i);
        }
        asm volatile("cp.async.commit_group;");
        asm volatile("cp.async.wait_group 0;");
        __syncthreads();

        int tn = (t >> 5) * 2;
        int tm = (t & 31) * 4;

        float acc0[4] = {}, acc1[4] = {};
        for (int kt = 0; kt < 4; kt++) {
            if (kt < 3) {
                const float4* src = (const float4*)(Rb + (size_t)(kt + 1) * 32 * NF);
                float4* dst = (float4*)&msh[(kt + 1) & 1][0][0];
                #pragma unroll
                for (int i = 0; i < 4; i++)
                    cp_async16(dst + t + 256 * i, src + t + 256 * i);
                asm volatile("cp.async.commit_group;");
                asm volatile("cp.async.wait_group 1;");
            } else {
                asm volatile("cp.async.wait_group 0;");
            }
            __syncthreads();

            const float (*mb)[NF] = msh[kt & 1];
            #pragma unroll
            for (int kk4 = 0; kk4 < 8; kk4++) {
                float cva[4], cvb[4];
                *(float4*)cva = *(const float4*)&csh[tn + 0][kt * 32 + kk4 * 4];
                *(float4*)cvb = *(const float4*)&csh[tn + 1][kt * 32 + kk4 * 4];
                #pragma unroll
                for (int j = 0; j < 4; j++) {
                    float4 mv = *(const float4*)&mb[kk4 * 4 + j][tm];
                    acc0[0] += cva[j] * mv.x; acc0[1] += cva[j] * mv.y;
                    acc0[2] += cva[j] * mv.z; acc0[3] += cva[j] * mv.w;
                    acc1[0] += cvb[j] * mv.x; acc1[1] += cvb[j] * mv.y;
                    acc1[2] += cvb[j] * mv.z; acc1[3] += cvb[j] * mv.w;
                }
            }
            __syncthreads();
        }

        float4 f0, f1;
        {
            float4 mm = *(const float4*)&msm[tn + 0][tm];
            float4 pp = *(const float4*)&csh[tn + 0][tm];
            f0.x = mm.x + 0.9f * pp.x + acc0[0];
            f0.y = mm.y + 0.9f * pp.y + acc0[1];
            f0.z = mm.z + 0.9f * pp.z + acc0[2];
            f0.w = mm.w + 0.9f * pp.w + acc0[3];
            mm = *(const float4*)&msm[tn + 1][tm];
            pp = *(const float4*)&csh[tn + 1][tm];
            f1.x = mm.x + 0.9f * pp.x + acc1[0];
            f1.y = mm.y + 0.9f * pp.y + acc1[1];
            f1.z = mm.z + 0.9f * pp.z + acc1[2];
            f1.w = mm.w + 0.9f * pp.w + acc1[3];
        }
        __syncthreads();
        *(float4*)&csh[tn + 0][tm] = f0;
        *(float4*)&csh[tn + 1][tm] = f1;
        __syncthreads();
        {
            int m = t >> 1, half = (t & 1) * 8;
            float v[8];
            #pragma unroll
            for (int i = 0; i < 8; i++) v[i] = csh[half + i][m];
            float* dstT = g_finalT + ((size_t)b * NF + m) * NF + n0 + half;
            *(float4*)&dstT[0] = make_float4(v[0], v[1], v[2], v[3]);
            *(float4*)&dstT[4] = make_float4(v[4], v[5], v[6], v[7]);
        }
        return;
    }

    // ---------------- sigma stream ----------------
    int id = bid - 256;
    int b = id >> 7;
    int m = id & 127;
    float* qsh = (float*)shraw;          // 1KB
    float* sig = qsh + DE;               // 0.5KB

    qsh[t] = g_query[b * DE + t];
    __syncthreads();

    int w = t >> 5, lane = t & 31;
    int qq = lane >> 3, sub = lane & 7;
    const float4* qp = (const float4*)qsh;
    const float* febase = fe + (((size_t)b * NF) * NF + m) * DE;

    float4 cur[8];
    {
        const float4* row = (const float4*)(febase + (size_t)(w + 8 * qq) * NF * DE);
        #pragma unroll
        for (int c = 0; c < 8; c++) cur[c] = __ldcs(&row[sub + 8 * c]);
    }

    #pragma unroll
    for (int j = 0; j < 4; j++) {
        float4 nxt[8];
        if (j < 3) {
            int n2 = w + 8 * (4 * (j + 1) + qq);
            const float4* row = (const float4*)(febase + (size_t)n2 * NF * DE);
            #pragma unroll
            for (int c = 0; c < 8; c++) nxt[c] = __ldcs(&row[sub + 8 * c]);
        }

        float sA = 0.f, sB = 0.f;
        #pragma unroll
        for (int c = 0; c < 8; c += 2) {
            float4 q0 = qp[sub + 8 * c];
            float4 q1 = qp[sub + 8 * (c + 1)];
            sA += cur[c].x * q0.x + cur[c].y * q0.y
                + cur[c].z * q0.z + cur[c].w * q0.w;
            sB += cur[c+1].x * q1.x + cur[c+1].y * q1.y
                + cur[c+1].z * q1.z + cur[c+1].w * q1.w;
        }
        float s = sA + sB;
        s += __shfl_xor_sync(~0u, s, 1);
        s += __shfl_xor_sync(~0u, s, 2);
        s += __shfl_xor_sync(~0u, s, 4);
        int n = w + 8 * (4 * j + qq);
        if (sub == 0) sig[n] = 1.f / (1.f + __expf(-s));

        #pragma unroll
        for (int c = 0; c < 8; c++) cur[c] = nxt[c];
    }
    __syncthreads();
    if (t < NF)
        g_sig[((size_t)b * NF + m) * NF + t] = sig[t];
}

// ============================================================================
// Kernel 3: masked contraction + norm + blend + all outputs.
// grid(B), block(512).
// ============================================================================
__global__ __launch_bounds__(512) void k3_final(
    const float* __restrict__ att_stack, const float* __restrict__ stack_ptr,
    float* __restrict__ out)
{
    int b = blockIdx.x;
    int t = threadIdx.x;
    __shared__ float ash[NF * G];
    __shared__ float att[NF * G];
    __shared__ float norm[G];
    __shared__ float sps[SL];

    if (t < NF * G) ash[t] = g_attin[b * NF * G + t];
    if (t < SL) sps[t] = stack_ptr[b * SL + t];
    __syncthreads();

    int w = t >> 5, lane = t & 31;
    const float4* ap = (const float4*)ash;
    float4 a01 = ap[2 * lane], a23 = ap[2 * lane + 1];

    #pragma unroll
    for (int r = 0; r < 8; r++) {
        int m = w + 16 * r;
        const float4* fr = (const float4*)(g_finalT + ((size_t)b * NF + m) * NF);
        const float4* sr = (const float4*)(g_sig    + ((size_t)b * NF + m) * NF);
        float4 f = fr[lane];
        float4 s = sr[lane];
        float w0 = f.x * s.x, w1 = f.y * s.y, w2 = f.z * s.z, w3 = f.w * s.w;
        float p0 = w0 * a01.x + w1 * a01.z + w2 * a23.x + w3 * a23.z;
        float p1 = w0 * a01.y + w1 * a01.w + w2 * a23.y + w3 * a23.w;
        #pragma unroll
        for (int o = 16; o; o >>= 1) {
            p0 += __shfl_xor_sync(~0u, p0, o);
            p1 += __shfl_xor_sync(~0u, p1, o);
        }
        if (lane == 0) { att[m * 2] = p0; att[m * 2 + 1] = p1; }
    }
    __syncthreads();

    if (t < 64) {
        int g = t >> 5, ln = t & 31;
        float mx = -1e30f;
        for (int i = ln; i < NF; i += 32) mx = fmaxf(mx, att[i * G + g]);
        #pragma unroll
        for (int o = 16; o; o >>= 1) mx = fmaxf(mx, __shfl_xor_sync(~0u, mx, o));
        if (ln == 0) norm[g] = (mx <= 1.f) ? 1.f : mx;
    }
    __syncthreads();

    const float* asb = att_stack + (size_t)b * NF * G * SL;
    float* ob = out + (size_t)b * NF * G * SL;
    for (int idx = t; idx < NF * G * SL; idx += 512) {
        int s = idx & 7;
        int g = (idx >> 3) & 1;
        int n = idx >> 4;
        float a  = att[n * G + g] / norm[g];
        float sp = sps[s];
        ob[idx] = a * sp + asb[idx] * (1.f - sp);
    }
    if (t < SL) out[(size_t)B * NF * G * SL + b * SL + t] = sps[t];
    float* z = out + (size_t)B * NF * G * SL + (size_t)B * SL;
    for (int i = t; i < DH; i += 512) {
        z[(size_t)b * DH + i] = 0.f;
        z[(size_t)B * DH + (size_t)b * DH + i] = 0.f;
    }
}

// ============================================================================
extern "C" void kernel_launch(void* const* d_in, const int* in_sizes, int n_in,
                              void* d_out, int out_size)
{
    const float* feat_edge = (const float*)d_in[2];
    const float* c_i       = (const float*)d_in[3];
    const float* relmask   = (const float*)d_in[4];
    const float* att_stack = (const float*)d_in[5];
    const float* stack_ptr = (const float*)d_in[6];
    const float* map_c_w   = (const float*)d_in[8];
    const float* map_c_b   = (const float*)d_in[9];
    float* out = (float*)d_out;

    k1_bitP_query<<<64, 256>>>(relmask, c_i, map_c_w, map_c_b,
                               att_stack, stack_ptr);
    k2_prepB_sigma<<<256 + B * NF, 256>>>(relmask, feat_edge);
    k3_final<<<B, 512>>>(att_stack, stack_ptr, out);
}

// round 9
// speedup vs baseline: 1.0895x; 1.0335x over previous
#include <cuda_runtime.h>
#include <math.h>

#define B   32
#define NF  128
#define DE  256
#define DH  512
#define G   2
#define SL  8

// ---- device scratch (no allocations allowed) ----
__device__ float g_query[B * DE];
__device__ float g_attin[B * NF * G];
__device__ float g_P[B * NF * NF];       // M @ M (integer counts as float)
__device__ float g_R[B * NF * NF];       // 0.81*M + 0.729*P
__device__ float g_finalT[B * NF * NF];  // final mask, transposed [b][m][n]
__device__ float g_sig[B * NF * NF];     // sigmoid(fe . q), layout [b][m][n]

__device__ __forceinline__ void cp_async16(void* smem_dst, const void* gmem_src) {
    unsigned sa = (unsigned)__cvta_generic_to_shared(smem_dst);
    asm volatile("cp.async.ca.shared.global [%0], [%1], 16;" :: "r"(sa), "l"(gmem_src));
}

// ============================================================================
// Kernel 1: grid(288), block(256).
//   bid < 256 : query tile — block (b = bid>>3, dchunk = bid&7) computes
//               query[b, dchunk*32 .. +32) = c_i[b,:] @ W[rows]^T + bias.
//               W slice = 64KB/block; W lives in L2 after wave start.
//   bid >= 256: bitP — P = M@M via ballot-pack + popcount (M is {0,1} exact),
//               R = 0.81M + 0.729P; plus att_in einsum for that b.
// ============================================================================
__global__ __launch_bounds__(256) void k1_query_bitP(
    const float* __restrict__ relmask,
    const float* __restrict__ c_i, const float* __restrict__ W,
    const float* __restrict__ bias,
    const float* __restrict__ att_stack, const float* __restrict__ stack_ptr)
{
    int bid = blockIdx.x;
    int t = threadIdx.x;

    if (bid < 256) {
        // ---------------- query tile ----------------
        int b  = bid >> 3;
        int d0 = (bid & 7) * 32;
        __shared__ float qc[DH];
        qc[t]       = c_i[b * DH + t];
        qc[t + 256] = c_i[b * DH + t + 256];
        __syncthreads();

        int w = t >> 5, lane = t & 31;
        #pragma unroll
        for (int i = 0; i < 4; i++) {
            int d = d0 + w * 4 + i;
            const float* Wr = W + (size_t)d * DH;
            float s = 0.f;
            #pragma unroll
            for (int k = 0; k < DH / 32; k++)
                s += Wr[lane + 32 * k] * qc[lane + 32 * k];
            #pragma unroll
            for (int o = 16; o; o >>= 1) s += __shfl_xor_sync(~0u, s, o);
            if (lane == 0) g_query[b * DE + d] = s + bias[d];
        }
        return;
    }

    // ---------------- bitP (+ att_in) ----------------
    int b = bid - 256;
    const float* Mb = relmask + (size_t)b * NF * NF;

    __shared__ unsigned rowbits[NF][4];      // row n bits over k
    __shared__ unsigned colbits[NF][5];      // col m bits over k (padded)

    int w = t >> 5, lane = t & 31;

    // pack rows via ballot: 512 words, 64 per warp, coalesced 128B loads
    for (int Wd = w; Wd < 512; Wd += 8) {
        int r = Wd >> 2, ww = Wd & 3;
        float v = Mb[r * NF + ww * 32 + lane];
        unsigned bal = __ballot_sync(~0u, v != 0.f);
        if (lane == 0) rowbits[r][ww] = bal;
    }

    // att_in[b,n,g] = sum_s att_stack[b,n,g,s] * stack_ptr[b,s] (tiny)
    {
        int n = t >> 1, g = t & 1;
        const float* as = att_stack + (((size_t)b * NF + n) * G + g) * SL;
        const float* sp = stack_ptr + b * SL;
        float s = 0.f;
        #pragma unroll
        for (int ss = 0; ss < SL; ss++) s += as[ss] * sp[ss];
        g_attin[(b * NF + n) * G + g] = s;
    }
    __syncthreads();

    // bit transpose: colbits[m][w] bit j = rowbits[32w+j] bit m
    for (int p = t; p < 512; p += 256) {
        int m = p >> 2, ww = p & 3;
        unsigned x = 0;
        #pragma unroll
        for (int j = 0; j < 32; j++)
            x |= (((rowbits[32 * ww + j][m >> 5] >> (m & 31)) & 1u) << j);
        colbits[m][ww] = x;
    }
    __syncthreads();

    // P[n][m] = popc over 4 words; R = 0.81*M + 0.729*P  (M from bits)
    float* Pb = g_P + (size_t)b * NF * NF;
    float* Rb = g_R + (size_t)b * NF * NF;
    for (int o = t; o < NF * NF; o += 256) {
        int n = o >> 7, m = o & 127;
        unsigned c = __popc(rowbits[n][0] & colbits[m][0])
                   + __popc(rowbits[n][1] & colbits[m][1])
                   + __popc(rowbits[n][2] & colbits[m][2])
                   + __popc(rowbits[n][3] & colbits[m][3]);
        float p = (float)c;
        float mm = (float)((rowbits[n][m >> 5] >> (m & 31)) & 1u);
        Pb[o] = p;
        Rb[o] = 0.81f * mm + 0.729f * p;
    }
}

// ============================================================================
// Kernel 2: combined launch.
//   bid < 256  : prepB — final = M + 0.9P + P@R, write final^T.
//   bid >= 256 : sigma stream — sig[b,m,n] = sigmoid(fe[b,n,m,:].q[b,:]).
// grid(256 + B*NF), block(256).  Shared memory overlaid (48KB).
// ============================================================================
__global__ __launch_bounds__(256) void k2_prepB_sigma(
    const float* __restrict__ relmask, const float* __restrict__ fe)
{
    __shared__ __align__(16) char shraw[49152];
    int bid = blockIdx.x;
    int t = threadIdx.x;

    if (bid < 256) {
        // ---------------- prepB ----------------
        int b  = bid >> 3;
        int n0 = (bid & 7) * 16;
        const float* Pb = g_P + (size_t)b * NF * NF;
        const float* Rb = g_R + (size_t)b * NF * NF;
        const float* Mb = relmask + (size_t)b * NF * NF;

        float (*csh)[NF] = (float(*)[NF])shraw;                 // 8KB: P rows
        float (*msm)[NF] = (float(*)[NF])(shraw + 8192);        // 8KB: M rows
        float (*msh)[32][NF] = (float(*)[32][NF])(shraw + 16384); // 32KB

        {
            const float4* srcP = (const float4*)(Pb + (size_t)n0 * NF);
            const float4* srcM = (const float4*)(Mb + (size_t)n0 * NF);
            float4* dstP = (float4*)&csh[0][0];
            float4* dstM = (float4*)&msm[0][0];
            cp_async16(dstP + t,       srcP + t);
            cp_async16(dstP + t + 256, srcP + t + 256);
            cp_async16(dstM + t,       srcM + t);
            cp_async16(dstM + t + 256, srcM + t + 256);
        }
        {
            const float4* src = (const float4*)Rb;
            float4* dst = (float4*)&msh[0][0][0];
            #pragma unroll
            for (int i = 0; i < 4; i++)
                cp_async16(dst + t + 256 * i, src + t + 256 * i);
        }
        asm volatile("cp.async.commit_group;");
        asm volatile("cp.async.wait_group 0;");
        __syncthreads();

        int tn = (t >> 5) * 2;
        int tm = (t & 31) * 4;

        float acc0[4] = {}, acc1[4] = {};
        for (int kt = 0; kt < 4; kt++) {
            if (kt < 3) {
                const float4* src = (const float4*)(Rb + (size_t)(kt + 1) * 32 * NF);
                float4* dst = (float4*)&msh[(kt + 1) & 1][0][0];
                #pragma unroll
                for (int i = 0; i < 4; i++)
                    cp_async16(dst + t + 256 * i, src + t + 256 * i);
                asm volatile("cp.async.commit_group;");
                asm volatile("cp.async.wait_group 1;");
            } else {
                asm volatile("cp.async.wait_group 0;");
            }
            __syncthreads();

            const float (*mb)[NF] = msh[kt & 1];
            #pragma unroll
            for (int kk4 = 0; kk4 < 8; kk4++) {
                float cva[4], cvb[4];
                *(float4*)cva = *(const float4*)&csh[tn + 0][kt * 32 + kk4 * 4];
                *(float4*)cvb = *(const float4*)&csh[tn + 1][kt * 32 + kk4 * 4];
                #pragma unroll
                for (int j = 0; j < 4; j++) {
                    float4 mv = *(const float4*)&mb[kk4 * 4 + j][tm];
                    acc0[0] += cva[j] * mv.x; acc0[1] += cva[j] * mv.y;
                    acc0[2] += cva[j] * mv.z; acc0[3] += cva[j] * mv.w;
                    acc1[0] += cvb[j] * mv.x; acc1[1] += cvb[j] * mv.y;
                    acc1[2] += cvb[j] * mv.z; acc1[3] += cvb[j] * mv.w;
                }
            }
            __syncthreads();
        }

        float4 f0, f1;
        {
            float4 mm = *(const float4*)&msm[tn + 0][tm];
            float4 pp = *(const float4*)&csh[tn + 0][tm];
            f0.x = mm.x + 0.9f * pp.x + acc0[0];
            f0.y = mm.y + 0.9f * pp.y + acc0[1];
            f0.z = mm.z + 0.9f * pp.z + acc0[2];
            f0.w = mm.w + 0.9f * pp.w + acc0[3];
            mm = *(const float4*)&msm[tn + 1][tm];
            pp = *(const float4*)&csh[tn + 1][tm];
            f1.x = mm.x + 0.9f * pp.x + acc1[0];
            f1.y = mm.y + 0.9f * pp.y + acc1[1];
            f1.z = mm.z + 0.9f * pp.z + acc1[2];
            f1.w = mm.w + 0.9f * pp.w + acc1[3];
        }
        __syncthreads();
        *(float4*)&csh[tn + 0][tm] = f0;
        *(float4*)&csh[tn + 1][tm] = f1;
        __syncthreads();
        {
            int m = t >> 1, half = (t & 1) * 8;
            float v[8];
            #pragma unroll
            for (int i = 0; i < 8; i++) v[i] = csh[half + i][m];
            float* dstT = g_finalT + ((size_t)b * NF + m) * NF + n0 + half;
            *(float4*)&dstT[0] = make_float4(v[0], v[1], v[2], v[3]);
            *(float4*)&dstT[4] = make_float4(v[4], v[5], v[6], v[7]);
        }
        return;
    }

    // ---------------- sigma stream ----------------
    int id = bid - 256;
    int b = id >> 7;
    int m = id & 127;
    float* qsh = (float*)shraw;          // 1KB
    float* sig = qsh + DE;               // 0.5KB

    qsh[t] = g_query[b * DE + t];
    __syncthreads();

    int w = t >> 5, lane = t & 31;
    int qq = lane >> 3, sub = lane & 7;
    const float4* qp = (const float4*)qsh;
    const float* febase = fe + (((size_t)b * NF) * NF + m) * DE;

    float4 cur[8];
    {
        const float4* row = (const float4*)(febase + (size_t)(w + 8 * qq) * NF * DE);
        #pragma unroll
        for (int c = 0; c < 8; c++) cur[c] = __ldcs(&row[sub + 8 * c]);
    }

    #pragma unroll
    for (int j = 0; j < 4; j++) {
        float4 nxt[8];
        if (j < 3) {
            int n2 = w + 8 * (4 * (j + 1) + qq);
            const float4* row = (const float4*)(febase + (size_t)n2 * NF * DE);
            #pragma unroll
            for (int c = 0; c < 8; c++) nxt[c] = __ldcs(&row[sub + 8 * c]);
        }

        float sA = 0.f, sB = 0.f;
        #pragma unroll
        for (int c = 0; c < 8; c += 2) {
            float4 q0 = qp[sub + 8 * c];
            float4 q1 = qp[sub + 8 * (c + 1)];
            sA += cur[c].x * q0.x + cur[c].y * q0.y
                + cur[c].z * q0.z + cur[c].w * q0.w;
            sB += cur[c+1].x * q1.x + cur[c+1].y * q1.y
                + cur[c+1].z * q1.z + cur[c+1].w * q1.w;
        }
        float s = sA + sB;
        s += __shfl_xor_sync(~0u, s, 1);
        s += __shfl_xor_sync(~0u, s, 2);
        s += __shfl_xor_sync(~0u, s, 4);
        int n = w + 8 * (4 * j + qq);
        if (sub == 0) sig[n] = 1.f / (1.f + __expf(-s));

        #pragma unroll
        for (int c = 0; c < 8; c++) cur[c] = nxt[c];
    }
    __syncthreads();
    if (t < NF)
        g_sig[((size_t)b * NF + m) * NF + t] = sig[t];
}

// ============================================================================
// Kernel 3: masked contraction + norm + blend + all outputs.
// grid(B), block(512).
// ============================================================================
__global__ __launch_bounds__(512) void k3_final(
    const float* __restrict__ att_stack, const float* __restrict__ stack_ptr,
    float* __restrict__ out)
{
    int b = blockIdx.x;
    int t = threadIdx.x;
    __shared__ float ash[NF * G];
    __shared__ float att[NF * G];
    __shared__ float norm[G];
    __shared__ float sps[SL];

    if (t < NF * G) ash[t] = g_attin[b * NF * G + t];
    if (t < SL) sps[t] = stack_ptr[b * SL + t];
    __syncthreads();

    int w = t >> 5, lane = t & 31;
    const float4* ap = (const float4*)ash;
    float4 a01 = ap[2 * lane], a23 = ap[2 * lane + 1];

    #pragma unroll
    for (int r = 0; r < 8; r++) {
        int m = w + 16 * r;
        const float4* fr = (const float4*)(g_finalT + ((size_t)b * NF + m) * NF);
        const float4* sr = (const float4*)(g_sig    + ((size_t)b * NF + m) * NF);
        float4 f = fr[lane];
        float4 s = sr[lane];
        float w0 = f.x * s.x, w1 = f.y * s.y, w2 = f.z * s.z, w3 = f.w * s.w;
        float p0 = w0 * a01.x + w1 * a01.z + w2 * a23.x + w3 * a23.z;
        float p1 = w0 * a01.y + w1 * a01.w + w2 * a23.y + w3 * a23.w;
        #pragma unroll
        for (int o = 16; o; o >>= 1) {
            p0 += __shfl_xor_sync(~0u, p0, o);
            p1 += __shfl_xor_sync(~0u, p1, o);
        }
        if (lane == 0) { att[m * 2] = p0; att[m * 2 + 1] = p1; }
    }
    __syncthreads();

    if (t < 64) {
        int g = t >> 5, ln = t & 31;
        float mx = -1e30f;
        for (int i = ln; i < NF; i += 32) mx = fmaxf(mx, att[i * G + g]);
        #pragma unroll
        for (int o = 16; o; o >>= 1) mx = fmaxf(mx, __shfl_xor_sync(~0u, mx, o));
        if (ln == 0) norm[g] = (mx <= 1.f) ? 1.f : mx;
    }
    __syncthreads();

    const float* asb = att_stack + (size_t)b * NF * G * SL;
    float* ob = out + (size_t)b * NF * G * SL;
    for (int idx = t; idx < NF * G * SL; idx += 512) {
        int s = idx & 7;
        int g = (idx >> 3) & 1;
        int n = idx >> 4;
        float a  = att[n * G + g] / norm[g];
        float sp = sps[s];
        ob[idx] = a * sp + asb[idx] * (1.f - sp);
    }
    if (t < SL) out[(size_t)B * NF * G * SL + b * SL + t] = sps[t];
    float* z = out + (size_t)B * NF * G * SL + (size_t)B * SL;
    for (int i = t; i < DH; i += 512) {
        z[(size_t)b * DH + i] = 0.f;
        z[(size_t)B * DH + (size_t)b * DH + i] = 0.f;
    }
}

// ============================================================================
extern "C" void kernel_launch(void* const* d_in, const int* in_sizes, int n_in,
                              void* d_out, int out_size)
{
    const float* feat_edge = (const float*)d_in[2];
    const float* c_i       = (const float*)d_in[3];
    const float* relmask   = (const float*)d_in[4];
    const float* att_stack = (const float*)d_in[5];
    const float* stack_ptr = (const float*)d_in[6];
    const float* map_c_w   = (const float*)d_in[8];
    const float* map_c_b   = (const float*)d_in[9];
    float* out = (float*)d_out;

    k1_query_bitP<<<288, 256>>>(relmask, c_i, map_c_w, map_c_b,
                                att_stack, stack_ptr);
    k2_prepB_sigma<<<256 + B * NF, 256>>>(relmask, feat_edge);
    k3_final<<<B, 512>>>(att_stack, stack_ptr, out);
}

// round 10
// speedup vs baseline: 1.1799x; 1.0829x over previous
#include <cuda_runtime.h>
#include <math.h>

#define B   32
#define NF  128
#define DE  256
#define DH  512
#define G   2
#define SL  8

// ---- device scratch (no allocations allowed) ----
__device__ float g_query[B * DE];
__device__ float g_attin[B * NF * G];
__device__ float g_P[B * NF * NF];       // M @ M (integer counts as float)
__device__ float g_R[B * NF * NF];       // 0.81*M + 0.729*P
__device__ float g_finalT[B * NF * NF];  // final mask, transposed [b][m][n]
__device__ float g_sig[B * NF * NF];     // sigmoid(fe . q), layout [b][m][n]

__device__ __forceinline__ void cp_async16(void* smem_dst, const void* gmem_src) {
    unsigned sa = (unsigned)__cvta_generic_to_shared(smem_dst);
    asm volatile("cp.async.ca.shared.global [%0], [%1], 16;" :: "r"(sa), "l"(gmem_src));
}

// ============================================================================
// Kernel 1: grid(288), block(256).
//   bid < 256 : query tile — block (b, dchunk) computes 32 query outputs.
//               W loads are float4, lane-consecutive (coalesced), 4 indep
//               chains per d, 4 d's unrolled -> high MLP.
//   bid >= 256: bitP — 8-deep load batching before ballots (MLP=8), then
//               bit-transpose + popcount P = M@M; R = 0.81M + 0.729P; att_in.
// ============================================================================
__global__ __launch_bounds__(256) void k1_query_bitP(
    const float* __restrict__ relmask,
    const float* __restrict__ c_i, const float* __restrict__ W,
    const float* __restrict__ bias,
    const float* __restrict__ att_stack, const float* __restrict__ stack_ptr)
{
    int bid = blockIdx.x;
    int t = threadIdx.x;

    if (bid < 256) {
        // ---------------- query tile ----------------
        int b  = bid >> 3;
        int d0 = (bid & 7) * 32;
        __shared__ float qc[DH];
        qc[t]       = c_i[b * DH + t];
        qc[t + 256] = c_i[b * DH + t + 256];
        __syncthreads();

        int w = t >> 5, lane = t & 31;
        const float4* qc4 = (const float4*)qc;

        // 4 d's per warp; preload all 16 float4 W values first (MLP 16)
        float4 wv[4][4];
        #pragma unroll
        for (int i = 0; i < 4; i++) {
            int d = d0 + w * 4 + i;
            const float4* Wr = (const float4*)(W + (size_t)d * DH);
            #pragma unroll
            for (int jj = 0; jj < 4; jj++)
                wv[i][jj] = Wr[lane + 32 * jj];
        }
        #pragma unroll
        for (int i = 0; i < 4; i++) {
            int d = d0 + w * 4 + i;
            float s = 0.f;
            #pragma unroll
            for (int jj = 0; jj < 4; jj++) {
                float4 q = qc4[lane + 32 * jj];
                s += wv[i][jj].x * q.x + wv[i][jj].y * q.y
                   + wv[i][jj].z * q.z + wv[i][jj].w * q.w;
            }
            #pragma unroll
            for (int o = 16; o; o >>= 1) s += __shfl_xor_sync(~0u, s, o);
            if (lane == 0) g_query[b * DE + d] = s + bias[d];
        }
        return;
    }

    // ---------------- bitP (+ att_in) ----------------
    int b = bid - 256;
    const float* Mb = relmask + (size_t)b * NF * NF;

    __shared__ unsigned rowbits[NF][4];      // row n bits over k
    __shared__ unsigned colbits[NF][5];      // col m bits over k (padded)

    int w = t >> 5, lane = t & 31;

    // pack rows: 512 warp-tasks over 8 warps = 64 each.
    // batch 8 loads into registers BEFORE any ballot -> MLP 8, not 1.
    #pragma unroll
    for (int g8 = 0; g8 < 8; g8++) {
        float v[8];
        #pragma unroll
        for (int i = 0; i < 8; i++) {
            int Wd = w + 8 * (8 * g8 + i);          // warp-task id
            int r = Wd >> 2, ww = Wd & 3;
            v[i] = Mb[r * NF + ww * 32 + lane];
        }
        #pragma unroll
        for (int i = 0; i < 8; i++) {
            int Wd = w + 8 * (8 * g8 + i);
            int r = Wd >> 2, ww = Wd & 3;
            unsigned bal = __ballot_sync(~0u, v[i] != 0.f);
            if (lane == 0) rowbits[r][ww] = bal;
        }
    }

    // att_in[b,n,g] = sum_s att_stack[b,n,g,s] * stack_ptr[b,s] (tiny)
    {
        int n = t >> 1, g = t & 1;
        const float* as = att_stack + (((size_t)b * NF + n) * G + g) * SL;
        const float* sp = stack_ptr + b * SL;
        float s = 0.f;
        #pragma unroll
        for (int ss = 0; ss < SL; ss++) s += as[ss] * sp[ss];
        g_attin[(b * NF + n) * G + g] = s;
    }
    __syncthreads();

    // bit transpose: colbits[m][w] bit j = rowbits[32w+j] bit m
    for (int p = t; p < 512; p += 256) {
        int m = p >> 2, ww = p & 3;
        unsigned x = 0;
        #pragma unroll
        for (int j = 0; j < 32; j++)
            x |= (((rowbits[32 * ww + j][m >> 5] >> (m & 31)) & 1u) << j);
        colbits[m][ww] = x;
    }
    __syncthreads();

    // P[n][m] = popc over 4 words; R = 0.81*M + 0.729*P  (M from bits)
    float* Pb = g_P + (size_t)b * NF * NF;
    float* Rb = g_R + (size_t)b * NF * NF;
    for (int o = t; o < NF * NF; o += 256) {
        int n = o >> 7, m = o & 127;
        unsigned c = __popc(rowbits[n][0] & colbits[m][0])
                   + __popc(rowbits[n][1] & colbits[m][1])
                   + __popc(rowbits[n][2] & colbits[m][2])
                   + __popc(rowbits[n][3] & colbits[m][3]);
        float p = (float)c;
        float mm = (float)((rowbits[n][m >> 5] >> (m & 31)) & 1u);
        Pb[o] = p;
        Rb[o] = 0.81f * mm + 0.729f * p;
    }
}

// ============================================================================
// Kernel 2: combined launch.
//   bid < 256  : prepB — final = M + 0.9P + P@R, write final^T.
//   bid >= 256 : sigma stream — sig[b,m,n] = sigmoid(fe[b,n,m,:].q[b,:]).
// grid(256 + B*NF), block(256).  Shared memory overlaid (48KB).
// ============================================================================
__global__ __launch_bounds__(256) void k2_prepB_sigma(
    const float* __restrict__ relmask, const float* __restrict__ fe)
{
    __shared__ __align__(16) char shraw[49152];
    int bid = blockIdx.x;
    int t = threadIdx.x;

    if (bid < 256) {
        // ---------------- prepB ----------------
        int b  = bid >> 3;
        int n0 = (bid & 7) * 16;
        const float* Pb = g_P + (size_t)b * NF * NF;
        const float* Rb = g_R + (size_t)b * NF * NF;
        const float* Mb = relmask + (size_t)b * NF * NF;

        float (*csh)[NF] = (float(*)[NF])shraw;                 // 8KB: P rows
        float (*msm)[NF] = (float(*)[NF])(shraw + 8192);        // 8KB: M rows
        float (*msh)[32][NF] = (float(*)[32][NF])(shraw + 16384); // 32KB

        {
            const float4* srcP = (const float4*)(Pb + (size_t)n0 * NF);
            const float4* srcM = (const float4*)(Mb + (size_t)n0 * NF);
            float4* dstP = (float4*)&csh[0][0];
            float4* dstM = (float4*)&msm[0][0];
            cp_async16(dstP + t,       srcP + t);
            cp_async16(dstP + t + 256, srcP + t + 256);
            cp_async16(dstM + t,       srcM + t);
            cp_async16(dstM + t + 256, srcM + t + 256);
        }
        {
            const float4* src = (const float4*)Rb;
            float4* dst = (float4*)&msh[0][0][0];
            #pragma unroll
            for (int i = 0; i < 4; i++)
                cp_async16(dst + t + 256 * i, src + t + 256 * i);
        }
        asm volatile("cp.async.commit_group;");
        asm volatile("cp.async.wait_group 0;");
        __syncthreads();

        int tn = (t >> 5) * 2;
        int tm = (t & 31) * 4;

        float acc0[4] = {}, acc1[4] = {};
        for (int kt = 0; kt < 4; kt++) {
            if (kt < 3) {
                const float4* src = (const float4*)(Rb + (size_t)(kt + 1) * 32 * NF);
                float4* dst = (float4*)&msh[(kt + 1) & 1][0][0];
                #pragma unroll
                for (int i = 0; i < 4; i++)
                    cp_async16(dst + t + 256 * i, src + t + 256 * i);
                asm volatile("cp.async.commit_group;");
                asm volatile("cp.async.wait_group 1;");
            } else {
                asm volatile("cp.async.wait_group 0;");
            }
            __syncthreads();

            const float (*mb)[NF] = msh[kt & 1];
            #pragma unroll
            for (int kk4 = 0; kk4 < 8; kk4++) {
                float cva[4], cvb[4];
                *(float4*)cva = *(const float4*)&csh[tn + 0][kt * 32 + kk4 * 4];
                *(float4*)cvb = *(const float4*)&csh[tn + 1][kt * 32 + kk4 * 4];
                #pragma unroll
                for (int j = 0; j < 4; j++) {
                    float4 mv = *(const float4*)&mb[kk4 * 4 + j][tm];
                    acc0[0] += cva[j] * mv.x; acc0[1] += cva[j] * mv.y;
                    acc0[2] += cva[j] * mv.z; acc0[3] += cva[j] * mv.w;
                    acc1[0] += cvb[j] * mv.x; acc1[1] += cvb[j] * mv.y;
                    acc1[2] += cvb[j] * mv.z; acc1[3] += cvb[j] * mv.w;
                }
            }
            __syncthreads();
        }

        float4 f0, f1;
        {
            float4 mm = *(const float4*)&msm[tn + 0][tm];
            float4 pp = *(const float4*)&csh[tn + 0][tm];
            f0.x = mm.x + 0.9f * pp.x + acc0[0];
            f0.y = mm.y + 0.9f * pp.y + acc0[1];
            f0.z = mm.z + 0.9f * pp.z + acc0[2];
            f0.w = mm.w + 0.9f * pp.w + acc0[3];
            mm = *(const float4*)&msm[tn + 1][tm];
            pp = *(const float4*)&csh[tn + 1][tm];
            f1.x = mm.x + 0.9f * pp.x + acc1[0];
            f1.y = mm.y + 0.9f * pp.y + acc1[1];
            f1.z = mm.z + 0.9f * pp.z + acc1[2];
            f1.w = mm.w + 0.9f * pp.w + acc1[3];
        }
        __syncthreads();
        *(float4*)&csh[tn + 0][tm] = f0;
        *(float4*)&csh[tn + 1][tm] = f1;
        __syncthreads();
        {
            int m = t >> 1, half = (t & 1) * 8;
            float v[8];
            #pragma unroll
            for (int i = 0; i < 8; i++) v[i] = csh[half + i][m];
            float* dstT = g_finalT + ((size_t)b * NF + m) * NF + n0 + half;
            *(float4*)&dstT[0] = make_float4(v[0], v[1], v[2], v[3]);
            *(float4*)&dstT[4] = make_float4(v[4], v[5], v[6], v[7]);
        }
        return;
    }

    // ---------------- sigma stream ----------------
    int id = bid - 256;
    int b = id >> 7;
    int m = id & 127;
    float* qsh = (float*)shraw;          // 1KB
    float* sig = qsh + DE;               // 0.5KB

    qsh[t] = g_query[b * DE + t];
    __syncthreads();

    int w = t >> 5, lane = t & 31;
    int qq = lane >> 3, sub = lane & 7;
    const float4* qp = (const float4*)qsh;
    const float* febase = fe + (((size_t)b * NF) * NF + m) * DE;

    float4 cur[8];
    {
        const float4* row = (const float4*)(febase + (size_t)(w + 8 * qq) * NF * DE);
        #pragma unroll
        for (int c = 0; c < 8; c++) cur[c] = __ldcs(&row[sub + 8 * c]);
    }

    #pragma unroll
    for (int j = 0; j < 4; j++) {
        float4 nxt[8];
        if (j < 3) {
            int n2 = w + 8 * (4 * (j + 1) + qq);
            const float4* row = (const float4*)(febase + (size_t)n2 * NF * DE);
            #pragma unroll
            for (int c = 0; c < 8; c++) nxt[c] = __ldcs(&row[sub + 8 * c]);
        }

        float sA = 0.f, sB = 0.f;
        #pragma unroll
        for (int c = 0; c < 8; c += 2) {
            float4 q0 = qp[sub + 8 * c];
            float4 q1 = qp[sub + 8 * (c + 1)];
            sA += cur[c].x * q0.x + cur[c].y * q0.y
                + cur[c].z * q0.z + cur[c].w * q0.w;
            sB += cur[c+1].x * q1.x + cur[c+1].y * q1.y
                + cur[c+1].z * q1.z + cur[c+1].w * q1.w;
        }
        float s = sA + sB;
        s += __shfl_xor_sync(~0u, s, 1);
        s += __shfl_xor_sync(~0u, s, 2);
        s += __shfl_xor_sync(~0u, s, 4);
        int n = w + 8 * (4 * j + qq);
        if (sub == 0) sig[n] = 1.f / (1.f + __expf(-s));

        #pragma unroll
        for (int c = 0; c < 8; c++) cur[c] = nxt[c];
    }
    __syncthreads();
    if (t < NF)
        g_sig[((size_t)b * NF + m) * NF + t] = sig[t];
}

// ============================================================================
// Kernel 3: masked contraction + norm + blend + all outputs.
// grid(B), block(512).
// ============================================================================
__global__ __launch_bounds__(512) void k3_final(
    const float* __restrict__ att_stack, const float* __restrict__ stack_ptr,
    float* __restrict__ out)
{
    int b = blockIdx.x;
    int t = threadIdx.x;
    __shared__ float ash[NF * G];
    __shared__ float att[NF * G];
    __shared__ float norm[G];
    __shared__ float sps[SL];

    if (t < NF * G) ash[t] = g_attin[b * NF * G + t];
    if (t < SL) sps[t] = stack_ptr[b * SL + t];
    __syncthreads();

    int w = t >> 5, lane = t & 31;
    const float4* ap = (const float4*)ash;
    float4 a01 = ap[2 * lane], a23 = ap[2 * lane + 1];

    #pragma unroll
    for (int r = 0; r < 8; r++) {
        int m = w + 16 * r;
        const float4* fr = (const float4*)(g_finalT + ((size_t)b * NF + m) * NF);
        const float4* sr = (const float4*)(g_sig    + ((size_t)b * NF + m) * NF);
        float4 f = fr[lane];
        float4 s = sr[lane];
        float w0 = f.x * s.x, w1 = f.y * s.y, w2 = f.z * s.z, w3 = f.w * s.w;
        float p0 = w0 * a01.x + w1 * a01.z + w2 * a23.x + w3 * a23.z;
        float p1 = w0 * a01.y + w1 * a01.w + w2 * a23.y + w3 * a23.w;
        #pragma unroll
        for (int o = 16; o; o >>= 1) {
            p0 += __shfl_xor_sync(~0u, p0, o);
            p1 += __shfl_xor_sync(~0u, p1, o);
        }
        if (lane == 0) { att[m * 2] = p0; att[m * 2 + 1] = p1; }
    }
    __syncthreads();

    if (t < 64) {
        int g = t >> 5, ln = t & 31;
        float mx = -1e30f;
        for (int i = ln; i < NF; i += 32) mx = fmaxf(mx, att[i * G + g]);
        #pragma unroll
        for (int o = 16; o; o >>= 1) mx = fmaxf(mx, __shfl_xor_sync(~0u, mx, o));
        if (ln == 0) norm[g] = (mx <= 1.f) ? 1.f : mx;
    }
    __syncthreads();

    const float* asb = att_stack + (size_t)b * NF * G * SL;
    float* ob = out + (size_t)b * NF * G * SL;
    for (int idx = t; idx < NF * G * SL; idx += 512) {
        int s = idx & 7;
        int g = (idx >> 3) & 1;
        int n = idx >> 4;
        float a  = att[n * G + g] / norm[g];
        float sp = sps[s];
        ob[idx] = a * sp + asb[idx] * (1.f - sp);
    }
    if (t < SL) out[(size_t)B * NF * G * SL + b * SL + t] = sps[t];
    float* z = out + (size_t)B * NF * G * SL + (size_t)B * SL;
    for (int i = t; i < DH; i += 512) {
        z[(size_t)b * DH + i] = 0.f;
        z[(size_t)B * DH + (size_t)b * DH + i] = 0.f;
    }
}

// ============================================================================
extern "C" void kernel_launch(void* const* d_in, const int* in_sizes, int n_in,
                              void* d_out, int out_size)
{
    const float* feat_edge = (const float*)d_in[2];
    const float* c_i       = (const float*)d_in[3];
    const float* relmask   = (const float*)d_in[4];
    const float* att_stack = (const float*)d_in[5];
    const float* stack_ptr = (const float*)d_in[6];
    const float* map_c_w   = (const float*)d_in[8];
    const float* map_c_b   = (const float*)d_in[9];
    float* out = (float*)d_out;

    k1_query_bitP<<<288, 256>>>(relmask, c_i, map_c_w, map_c_b,
                                att_stack, stack_ptr);
    k2_prepB_sigma<<<256 + B * NF, 256>>>(relmask, feat_edge);
    k3_final<<<B, 512>>>(att_stack, stack_ptr, out);
}